// round 6
// baseline (speedup 1.0000x reference)
#include <cuda_runtime.h>
#include <cuda_fp16.h>

// bg: (1, 4, 32, 32, 32, 16) f32   -> d_in[0]
// gm: (1, 1, 128, 128, 128) f32    -> d_in[1]
// out:(1, 4, 128, 128, 128) f32

#define GH 128
#define GWD 128
#define GD 128
#define H 32
#define W 32
#define D 32
#define UP 16
#define TH 2
#define TW 4
#define NCOL 8
#define ROWE 512                       // [z][t] entries per column plane
#define PLANE_E (NCOL * ROWE)
#define PLANE_BYTES (PLANE_E * 8)      // 32768

#define CH_STRIDE (H*W*D*UP)           // 524288
#define OUT_CH (GH*GWD*GD)             // 2097152

__device__ __forceinline__ __half2 u2h(unsigned int u) {
    __half2 h; *reinterpret_cast<unsigned int*>(&h) = u; return h;
}
__device__ __forceinline__ unsigned int h2u(__half2 h) {
    return *reinterpret_cast<unsigned int*>(&h);
}

__global__ void __launch_bounds__(256, 4)
bgrid_slice_kernel(const float* __restrict__ bg,
                   const float* __restrict__ gm,
                   float* __restrict__ out)
{
    extern __shared__ uint2 S_plane[];           // [col][z][t] fp16x4
    __shared__ uint4 WX3[TH];                    // 3-tap x weights per lh
    __shared__ uint4 WY3[TW];                    // 3-tap y weights per lw

    const float sx = 31.0f / 127.0f;
    const int gh0 = blockIdx.y * TH;
    const int gw0 = blockIdx.x * TW;
    const int X = (int)floorf((float)gh0 * sx);
    const int Y = (int)floorf((float)gw0 * sx);
    const int tid = threadIdx.x;

    // ---- tiny weight tables (3-tap padded, branch-free downstream) ----
    if (tid < 2 + 4) {
        int isY = (tid >= TH);
        int l = isY ? (tid - TH) : tid;
        int base = isY ? gw0 : gh0;
        int O = isY ? Y : X;
        float c = fminf((float)(base + l) * sx, 31.0f);
        float c0f = floorf(c);
        float f = c - c0f;
        int l0 = (int)c0f - O;                    // 0 or 1
        uint4 w3;
        if (l0 == 0) {
            w3.x = h2u(__float2half2_rn(1.f - f));
            w3.y = h2u(__float2half2_rn(f));
            w3.z = 0u;
        } else {
            w3.x = 0u;
            w3.y = h2u(__float2half2_rn(1.f - f));
            w3.z = h2u(__float2half2_rn(f));
        }
        w3.w = 0u;
        if (isY) WY3[l] = w3; else WX3[l] = w3;
    }
    __syncthreads();

    // ---- phase 1: stream 9 corner rows, blend in registers, STS planes ----
    int rowbase[9];
    #pragma unroll
    for (int r = 0; r < 9; r++) {
        int a = r / 3, b = r - a * 3;
        int gx = min(X + a, H - 1);
        int gy = min(Y + b, W - 1);
        rowbase[r] = (gx * W + gy) * ROWE;
    }

    #pragma unroll
    for (int k = 0; k < 2; k++) {
        const int zt = k * 256 + tid;

        uint2 T[12];                     // T[a][lw], a in 0..2
        #pragma unroll
        for (int a = 0; a < 3; a++) {
            uint2 R[3];
            #pragma unroll
            for (int b = 0; b < 3; b++) {
                int idx = rowbase[a * 3 + b] + zt;
                float f0 = bg[idx];
                float f1 = bg[idx + CH_STRIDE];
                float f2 = bg[idx + 2 * CH_STRIDE];
                float f3 = bg[idx + 3 * CH_STRIDE];
                R[b].x = h2u(__floats2half2_rn(f0, f1));
                R[b].y = h2u(__floats2half2_rn(f2, f3));
            }
            #pragma unroll
            for (int lw = 0; lw < 4; lw++) {
                uint4 wy = WY3[lw];
                __half2 w0 = u2h(wy.x), w1 = u2h(wy.y), w2 = u2h(wy.z);
                __half2 t01 = __hmul2(w0, u2h(R[0].x));
                t01 = __hfma2(w1, u2h(R[1].x), t01);
                t01 = __hfma2(w2, u2h(R[2].x), t01);
                __half2 t23 = __hmul2(w0, u2h(R[0].y));
                t23 = __hfma2(w1, u2h(R[1].y), t23);
                t23 = __hfma2(w2, u2h(R[2].y), t23);
                T[a*4 + lw].x = h2u(t01);
                T[a*4 + lw].y = h2u(t23);
            }
        }

        #pragma unroll
        for (int lh = 0; lh < TH; lh++) {
            uint4 wx = WX3[lh];
            __half2 w0 = u2h(wx.x), w1 = u2h(wx.y), w2 = u2h(wx.z);
            #pragma unroll
            for (int lw = 0; lw < 4; lw++) {
                __half2 o01 = __hmul2(w0, u2h(T[0*4 + lw].x));
                o01 = __hfma2(w1, u2h(T[1*4 + lw].x), o01);
                o01 = __hfma2(w2, u2h(T[2*4 + lw].x), o01);
                __half2 o23 = __hmul2(w0, u2h(T[0*4 + lw].y));
                o23 = __hfma2(w1, u2h(T[1*4 + lw].y), o23);
                o23 = __hfma2(w2, u2h(T[2*4 + lw].y), o23);
                uint2 o; o.x = h2u(o01); o.y = h2u(o23);
                S_plane[(lh*4 + lw) * ROWE + zt] = o;
            }
        }
    }
    __syncthreads();

    // ---- phase 2: gather, invariants hoisted ----
    // 8 cols x 128 gd = 1024 voxels, 4 per thread
    const int gd = tid & 127;
    const int hh = tid >> 7;

    float zc = fminf((float)gd * sx, 31.0f);
    float z0f = floorf(zc);
    float fz = zc - z0f;
    int z0 = (int)z0f;
    int z1 = min(z0 + 1, D - 1);
    const int z0o = z0 * 16;
    const int z1o = z1 * 16;
    const float wzA = 1.f - fz;

    float g[4];
    int obase[4];
    int poff[4];
    #pragma unroll
    for (int k = 0; k < 4; k++) {
        int c8 = 2 * k + hh;
        int gh = gh0 + (c8 >> 2);
        int gw = gw0 + (c8 & 3);
        obase[k] = (gh * GWD + gw) * GD + gd;
        poff[k] = c8 * ROWE;
    }
    #pragma unroll
    for (int k = 0; k < 4; k++) g[k] = __ldg(&gm[obase[k]]);

    #pragma unroll
    for (int k = 0; k < 4; k++) {
        float t = fminf(fmaxf(g[k] * 15.0f, 0.0f), 15.0f);
        float t0f = floorf(t);
        float ft = t - t0f;
        int t0 = (int)t0f;
        int t1 = min(t0 + 1, UP - 1);

        const uint2* P = S_plane + poff[k];
        uint2 e00 = P[z0o + t0];
        uint2 e01 = P[z0o + t1];
        uint2 e10 = P[z1o + t0];
        uint2 e11 = P[z1o + t1];

        float w00 = wzA * (1.f - ft);
        float w01 = wzA * ft;
        float w10 = fz * (1.f - ft);
        float w11 = fz * ft;

        float2 a01 = __half22float2(u2h(e00.x));
        float2 a23 = __half22float2(u2h(e00.y));
        float acc0 = a01.x * w00, acc1 = a01.y * w00;
        float acc2 = a23.x * w00, acc3 = a23.y * w00;

        a01 = __half22float2(u2h(e01.x)); a23 = __half22float2(u2h(e01.y));
        acc0 = fmaf(a01.x, w01, acc0); acc1 = fmaf(a01.y, w01, acc1);
        acc2 = fmaf(a23.x, w01, acc2); acc3 = fmaf(a23.y, w01, acc3);

        a01 = __half22float2(u2h(e10.x)); a23 = __half22float2(u2h(e10.y));
        acc0 = fmaf(a01.x, w10, acc0); acc1 = fmaf(a01.y, w10, acc1);
        acc2 = fmaf(a23.x, w10, acc2); acc3 = fmaf(a23.y, w10, acc3);

        a01 = __half22float2(u2h(e11.x)); a23 = __half22float2(u2h(e11.y));
        acc0 = fmaf(a01.x, w11, acc0); acc1 = fmaf(a01.y, w11, acc1);
        acc2 = fmaf(a23.x, w11, acc2); acc3 = fmaf(a23.y, w11, acc3);

        int ob = obase[k];
        out[ob]              = acc0;
        out[ob + OUT_CH]     = acc1;
        out[ob + 2 * OUT_CH] = acc2;
        out[ob + 3 * OUT_CH] = acc3;
    }
}

extern "C" void kernel_launch(void* const* d_in, const int* in_sizes, int n_in,
                              void* d_out, int out_size)
{
    const float* bg = (const float*)d_in[0];
    const float* gm = (const float*)d_in[1];
    float* out = (float*)d_out;

    cudaFuncSetAttribute(bgrid_slice_kernel,
                         cudaFuncAttributeMaxDynamicSharedMemorySize, PLANE_BYTES);

    dim3 grid(GWD / TW, GH / TH);   // 32 x 64 = 2048 blocks
    bgrid_slice_kernel<<<grid, 256, PLANE_BYTES>>>(bg, gm, out);
}

// round 7
// speedup vs baseline: 1.2194x; 1.2194x over previous
#include <cuda_runtime.h>
#include <cuda_fp16.h>

// bg: (1, 4, 32, 32, 32, 16) f32   -> d_in[0]
// gm: (1, 1, 128, 128, 128) f32    -> d_in[1]
// out:(1, 4, 128, 128, 128) f32

#define GH 128
#define GWD 128
#define GD 128
#define H 32
#define W 32
#define D 32
#define UP 16
#define TH 4
#define TW 4
#define ROWE 512                       // [z][t] entries per column plane
#define PLANE_E (16 * ROWE)
#define PLANE_BYTES (PLANE_E * 8)      // 65536

#define CH_STRIDE (H*W*D*UP)           // 524288
#define OUT_CH (GH*GWD*GD)             // 2097152

__device__ __forceinline__ __half2 u2h(unsigned int u) {
    __half2 h; *reinterpret_cast<unsigned int*>(&h) = u; return h;
}
__device__ __forceinline__ unsigned int h2u(__half2 h) {
    return *reinterpret_cast<unsigned int*>(&h);
}

__global__ void __launch_bounds__(256, 3)
bgrid_slice_kernel(const float* __restrict__ bg,
                   const float* __restrict__ gm,
                   float* __restrict__ out)
{
    extern __shared__ uint2 S_plane[];           // [col][z][t] fp16x4
    __shared__ uint4 WX3[TH];
    __shared__ uint4 WY3[TW];

    const float sx = 31.0f / 127.0f;
    const int gh0 = blockIdx.y * TH;
    const int gw0 = blockIdx.x * TW;
    const int X = (int)floorf((float)gh0 * sx);
    const int Y = (int)floorf((float)gw0 * sx);
    const int tid = threadIdx.x;

    // ---- tiny weight tables (3-tap padded, branch-free downstream) ----
    if (tid < 8) {
        int l = tid & 3;
        int base = (tid < 4) ? gh0 : gw0;
        int O = (tid < 4) ? X : Y;
        float c = fminf((float)(base + l) * sx, 31.0f);
        float c0f = floorf(c);
        float f = c - c0f;
        int l0 = (int)c0f - O;                    // 0 or 1
        uint4 w3;
        if (l0 == 0) {
            w3.x = h2u(__float2half2_rn(1.f - f));
            w3.y = h2u(__float2half2_rn(f));
            w3.z = 0u;
        } else {
            w3.x = 0u;
            w3.y = h2u(__float2half2_rn(1.f - f));
            w3.z = h2u(__float2half2_rn(f));
        }
        w3.w = 0u;
        if (tid < 4) WX3[l] = w3; else WY3[l] = w3;
    }
    __syncthreads();

    // ---- phase 1: zt-pair per thread, float2 loads, register blend, STS.128 ----
    {
        const int zt0 = tid * 2;                  // this thread's zt pair: zt0, zt0+1

        int rowbase[9];
        #pragma unroll
        for (int r = 0; r < 9; r++) {
            int a = r / 3, b = r - a * 3;
            int gx = min(X + a, H - 1);
            int gy = min(Y + b, W - 1);
            rowbase[r] = (gx * W + gy) * ROWE;
        }

        uint2 Rlo[9], Rhi[9];
        #pragma unroll
        for (int r = 0; r < 9; r++) {
            int idx = rowbase[r] + zt0;
            float2 c0 = *reinterpret_cast<const float2*>(&bg[idx]);
            float2 c1 = *reinterpret_cast<const float2*>(&bg[idx + CH_STRIDE]);
            float2 c2 = *reinterpret_cast<const float2*>(&bg[idx + 2 * CH_STRIDE]);
            float2 c3 = *reinterpret_cast<const float2*>(&bg[idx + 3 * CH_STRIDE]);
            Rlo[r].x = h2u(__floats2half2_rn(c0.x, c1.x));
            Rlo[r].y = h2u(__floats2half2_rn(c2.x, c3.x));
            Rhi[r].x = h2u(__floats2half2_rn(c0.y, c1.y));
            Rhi[r].y = h2u(__floats2half2_rn(c2.y, c3.y));
        }

        #pragma unroll
        for (int lw = 0; lw < 4; lw++) {
            uint4 wy = WY3[lw];
            __half2 v0 = u2h(wy.x), v1 = u2h(wy.y), v2 = u2h(wy.z);
            uint2 Tlo[3], Thi[3];
            #pragma unroll
            for (int a = 0; a < 3; a++) {
                __half2 t01 = __hmul2(v0, u2h(Rlo[a*3 + 0].x));
                t01 = __hfma2(v1, u2h(Rlo[a*3 + 1].x), t01);
                t01 = __hfma2(v2, u2h(Rlo[a*3 + 2].x), t01);
                __half2 t23 = __hmul2(v0, u2h(Rlo[a*3 + 0].y));
                t23 = __hfma2(v1, u2h(Rlo[a*3 + 1].y), t23);
                t23 = __hfma2(v2, u2h(Rlo[a*3 + 2].y), t23);
                Tlo[a].x = h2u(t01); Tlo[a].y = h2u(t23);
                t01 = __hmul2(v0, u2h(Rhi[a*3 + 0].x));
                t01 = __hfma2(v1, u2h(Rhi[a*3 + 1].x), t01);
                t01 = __hfma2(v2, u2h(Rhi[a*3 + 2].x), t01);
                t23 = __hmul2(v0, u2h(Rhi[a*3 + 0].y));
                t23 = __hfma2(v1, u2h(Rhi[a*3 + 1].y), t23);
                t23 = __hfma2(v2, u2h(Rhi[a*3 + 2].y), t23);
                Thi[a].x = h2u(t01); Thi[a].y = h2u(t23);
            }
            #pragma unroll
            for (int lh = 0; lh < 4; lh++) {
                uint4 wx = WX3[lh];
                __half2 w0 = u2h(wx.x), w1 = u2h(wx.y), w2 = u2h(wx.z);
                __half2 a01 = __hmul2(w0, u2h(Tlo[0].x));
                a01 = __hfma2(w1, u2h(Tlo[1].x), a01);
                a01 = __hfma2(w2, u2h(Tlo[2].x), a01);
                __half2 a23 = __hmul2(w0, u2h(Tlo[0].y));
                a23 = __hfma2(w1, u2h(Tlo[1].y), a23);
                a23 = __hfma2(w2, u2h(Tlo[2].y), a23);
                __half2 b01 = __hmul2(w0, u2h(Thi[0].x));
                b01 = __hfma2(w1, u2h(Thi[1].x), b01);
                b01 = __hfma2(w2, u2h(Thi[2].x), b01);
                __half2 b23 = __hmul2(w0, u2h(Thi[0].y));
                b23 = __hfma2(w1, u2h(Thi[1].y), b23);
                b23 = __hfma2(w2, u2h(Thi[2].y), b23);
                uint4 q;
                q.x = h2u(a01); q.y = h2u(a23);     // entry zt0
                q.z = h2u(b01); q.w = h2u(b23);     // entry zt0+1
                *reinterpret_cast<uint4*>(&S_plane[(lh*4 + lw) * ROWE + zt0]) = q;
            }
        }
    }
    __syncthreads();

    // ---- phase 2: gd-pair per thread; 16 cols x 64 pairs, 4 iters ----
    const int gdp = tid & 63;
    const int gd0 = gdp * 2;
    const int cbase = tid >> 6;                   // 0..3

    // two hoisted z-chains (gd0 and gd0+1)
    float zcA = fminf((float)gd0 * sx, 31.0f);
    float zA0f = floorf(zcA); float fzA = zcA - zA0f;
    int zA0 = (int)zA0f; int zA1 = min(zA0 + 1, D - 1);
    const int zA0o = zA0 * 16, zA1o = zA1 * 16;
    const float wzAa = 1.f - fzA;

    float zcB = fminf((float)(gd0 + 1) * sx, 31.0f);
    float zB0f = floorf(zcB); float fzB = zcB - zB0f;
    int zB0 = (int)zB0f; int zB1 = min(zB0 + 1, D - 1);
    const int zB0o = zB0 * 16, zB1o = zB1 * 16;
    const float wzBa = 1.f - fzB;

    float2 g[4];
    int obase[4];
    int poff[4];
    #pragma unroll
    for (int k = 0; k < 4; k++) {
        int c16 = k * 4 + cbase;
        int gh = gh0 + (c16 >> 2);
        int gw = gw0 + (c16 & 3);
        obase[k] = (gh * GWD + gw) * GD + gd0;
        poff[k] = c16 * ROWE;
    }
    #pragma unroll
    for (int k = 0; k < 4; k++)
        g[k] = *reinterpret_cast<const float2*>(&gm[obase[k]]);

    #pragma unroll
    for (int k = 0; k < 4; k++) {
        const uint2* P = S_plane + poff[k];

        // voxel A (gd0)
        float tA = fminf(fmaxf(g[k].x * 15.0f, 0.0f), 15.0f);
        float tA0f = floorf(tA); float ftA = tA - tA0f;
        int tA0 = (int)tA0f; int tA1 = min(tA0 + 1, UP - 1);
        uint2 eA00 = P[zA0o + tA0];
        uint2 eA01 = P[zA0o + tA1];
        uint2 eA10 = P[zA1o + tA0];
        uint2 eA11 = P[zA1o + tA1];

        // voxel B (gd0+1)
        float tB = fminf(fmaxf(g[k].y * 15.0f, 0.0f), 15.0f);
        float tB0f = floorf(tB); float ftB = tB - tB0f;
        int tB0 = (int)tB0f; int tB1 = min(tB0 + 1, UP - 1);
        uint2 eB00 = P[zB0o + tB0];
        uint2 eB01 = P[zB0o + tB1];
        uint2 eB10 = P[zB1o + tB0];
        uint2 eB11 = P[zB1o + tB1];

        float wA00 = wzAa * (1.f - ftA), wA01 = wzAa * ftA;
        float wA10 = fzA * (1.f - ftA),  wA11 = fzA * ftA;
        float wB00 = wzBa * (1.f - ftB), wB01 = wzBa * ftB;
        float wB10 = fzB * (1.f - ftB),  wB11 = fzB * ftB;

        float2 p01, p23;
        p01 = __half22float2(u2h(eA00.x)); p23 = __half22float2(u2h(eA00.y));
        float A0 = p01.x * wA00, A1 = p01.y * wA00, A2 = p23.x * wA00, A3 = p23.y * wA00;
        p01 = __half22float2(u2h(eA01.x)); p23 = __half22float2(u2h(eA01.y));
        A0 = fmaf(p01.x, wA01, A0); A1 = fmaf(p01.y, wA01, A1);
        A2 = fmaf(p23.x, wA01, A2); A3 = fmaf(p23.y, wA01, A3);
        p01 = __half22float2(u2h(eA10.x)); p23 = __half22float2(u2h(eA10.y));
        A0 = fmaf(p01.x, wA10, A0); A1 = fmaf(p01.y, wA10, A1);
        A2 = fmaf(p23.x, wA10, A2); A3 = fmaf(p23.y, wA10, A3);
        p01 = __half22float2(u2h(eA11.x)); p23 = __half22float2(u2h(eA11.y));
        A0 = fmaf(p01.x, wA11, A0); A1 = fmaf(p01.y, wA11, A1);
        A2 = fmaf(p23.x, wA11, A2); A3 = fmaf(p23.y, wA11, A3);

        p01 = __half22float2(u2h(eB00.x)); p23 = __half22float2(u2h(eB00.y));
        float B0 = p01.x * wB00, B1 = p01.y * wB00, B2 = p23.x * wB00, B3 = p23.y * wB00;
        p01 = __half22float2(u2h(eB01.x)); p23 = __half22float2(u2h(eB01.y));
        B0 = fmaf(p01.x, wB01, B0); B1 = fmaf(p01.y, wB01, B1);
        B2 = fmaf(p23.x, wB01, B2); B3 = fmaf(p23.y, wB01, B3);
        p01 = __half22float2(u2h(eB10.x)); p23 = __half22float2(u2h(eB10.y));
        B0 = fmaf(p01.x, wB10, B0); B1 = fmaf(p01.y, wB10, B1);
        B2 = fmaf(p23.x, wB10, B2); B3 = fmaf(p23.y, wB10, B3);
        p01 = __half22float2(u2h(eB11.x)); p23 = __half22float2(u2h(eB11.y));
        B0 = fmaf(p01.x, wB11, B0); B1 = fmaf(p01.y, wB11, B1);
        B2 = fmaf(p23.x, wB11, B2); B3 = fmaf(p23.y, wB11, B3);

        int ob = obase[k];
        *reinterpret_cast<float2*>(&out[ob])              = make_float2(A0, B0);
        *reinterpret_cast<float2*>(&out[ob + OUT_CH])     = make_float2(A1, B1);
        *reinterpret_cast<float2*>(&out[ob + 2 * OUT_CH]) = make_float2(A2, B2);
        *reinterpret_cast<float2*>(&out[ob + 3 * OUT_CH]) = make_float2(A3, B3);
    }
}

extern "C" void kernel_launch(void* const* d_in, const int* in_sizes, int n_in,
                              void* d_out, int out_size)
{
    const float* bg = (const float*)d_in[0];
    const float* gm = (const float*)d_in[1];
    float* out = (float*)d_out;

    cudaFuncSetAttribute(bgrid_slice_kernel,
                         cudaFuncAttributeMaxDynamicSharedMemorySize, PLANE_BYTES);

    dim3 grid(GWD / TW, GH / TH);   // 32 x 32 = 1024 blocks
    bgrid_slice_kernel<<<grid, 256, PLANE_BYTES>>>(bg, gm, out);
}